// round 2
// baseline (speedup 1.0000x reference)
#include <cuda_runtime.h>
#include <cuda_fp16.h>
#include <cstdint>

// ---------------- problem constants ----------------
constexpr int Bn = 4, Tn = 1024, Hn = 2048, Vn = 32000;
constexpr int TOK = Bn * Tn;            // 4096 tokens
constexpr int M_TILE = 128;
constexpr int N_TILE = 128;
constexpr int K_CHUNK = 32;
constexpr int MTILES = TOK / M_TILE;    // 32
constexpr int NTILES = Vn / N_TILE;     // 250
constexpr int KITERS = Hn / K_CHUNK;    // 64

// smem row padding: 40 halves (80 B) per 32-half row -> conflict-free ldmatrix
constexpr int SROW = 40;

// ---------------- device scratch (no runtime alloc allowed) ----------------
__device__ __half g_wh[2][(size_t)Vn * Hn];   // fp16 weights (policy, ref)
__device__ __half g_xh[2][(size_t)TOK * Hn];  // fp16 activations
__device__ float  g_partial[2][NTILES][TOK];  // per-ntile partial sumexp
__device__ float  g_sel[2][TOK];              // selected logits
__device__ float  g_logp[2][TOK];             // per-token logps

// ---------------- PTX helpers (baseline features only) ----------------
__device__ __forceinline__ uint32_t smem_u32(const void* p) {
    uint32_t a;
    asm("{ .reg .u64 t; cvta.to.shared.u64 t, %1; cvt.u32.u64 %0, t; }" : "=r"(a) : "l"(p));
    return a;
}

__device__ __forceinline__ void cp_async16(uint32_t dst, const void* src) {
    asm volatile("cp.async.cg.shared.global [%0], [%1], 16;" :: "r"(dst), "l"(src) : "memory");
}
#define CP_COMMIT() asm volatile("cp.async.commit_group;" ::: "memory")
#define CP_WAIT(n)  asm volatile("cp.async.wait_group %0;" :: "n"(n) : "memory")

__device__ __forceinline__ void ldsm_x4(uint32_t& r0, uint32_t& r1, uint32_t& r2, uint32_t& r3,
                                        uint32_t addr) {
    asm volatile("ldmatrix.sync.aligned.m8n8.x4.shared.b16 {%0,%1,%2,%3}, [%4];"
                 : "=r"(r0), "=r"(r1), "=r"(r2), "=r"(r3) : "r"(addr));
}

__device__ __forceinline__ void mma16816(float& d0, float& d1, float& d2, float& d3,
                                         uint32_t a0, uint32_t a1, uint32_t a2, uint32_t a3,
                                         uint32_t b0, uint32_t b1) {
    asm volatile(
        "mma.sync.aligned.m16n8k16.row.col.f32.f16.f16.f32 "
        "{%0,%1,%2,%3}, {%4,%5,%6,%7}, {%8,%9}, {%0,%1,%2,%3};"
        : "+f"(d0), "+f"(d1), "+f"(d2), "+f"(d3)
        : "r"(a0), "r"(a1), "r"(a2), "r"(a3), "r"(b0), "r"(b1));
}

// ---------------- convert kernels (fp32 -> fp16 scratch) ----------------
__global__ void convert_kernel(const float* __restrict__ src, __half* __restrict__ dst,
                               int n4) {
    int i = blockIdx.x * blockDim.x + threadIdx.x;
    const int stride = gridDim.x * blockDim.x;
    for (; i < n4; i += stride) {
        float4 v = reinterpret_cast<const float4*>(src)[i];
        __half2 lo = __floats2half2_rn(v.x, v.y);
        __half2 hi = __floats2half2_rn(v.z, v.w);
        uint2 o;
        o.x = reinterpret_cast<uint32_t&>(lo);
        o.y = reinterpret_cast<uint32_t&>(hi);
        reinterpret_cast<uint2*>(dst)[i] = o;
    }
}

// ---------------- fused GEMM + partial-softmax kernel ----------------
// grid = (MTILES, NTILES, 2); block = 256 threads (8 warps: 4 M x 2 N)
__global__ void __launch_bounds__(256, 1) gemm_kernel(const int* __restrict__ sel_ids) {
    __shared__ __align__(16) __half sA[2][M_TILE][SROW];
    __shared__ __align__(16) __half sB[2][N_TILE][SROW];
    __shared__ float rsum[2][M_TILE];

    const int tid = threadIdx.x;
    const int lane = tid & 31;
    const int wid = tid >> 5;
    const int warpM = wid >> 1;   // 0..3
    const int warpN = wid & 1;    // 0..1
    const int gz = blockIdx.z;
    const int nt = blockIdx.y;
    const int m0 = blockIdx.x * M_TILE;
    const int n0 = nt * N_TILE;

    const __half* __restrict__ X = g_xh[gz];
    const __half* __restrict__ W = g_wh[gz];

    const uint32_t sA_base = smem_u32(&sA[0][0][0]);
    const uint32_t sB_base = smem_u32(&sB[0][0][0]);
    constexpr uint32_t BUF_A = M_TILE * SROW * 2;  // bytes per A buffer
    constexpr uint32_t BUF_B = N_TILE * SROW * 2;

    // cp.async loader: 512 16B-chunks each for A and B; 256 threads x 2
    const int lr = tid >> 2;        // row within tile (0..63 per j)
    const int lc = tid & 3;         // 16B chunk within row (0..3)

    auto issue_load = [&](int p, int ki) {
        const __half* xg = X + (size_t)(m0) * Hn + ki * K_CHUNK;
        const __half* wg = W + (size_t)(n0) * Hn + ki * K_CHUNK;
        uint32_t a_dst = sA_base + p * BUF_A;
        uint32_t b_dst = sB_base + p * BUF_B;
#pragma unroll
        for (int j = 0; j < 2; j++) {
            int r = lr + j * 64;
            cp_async16(a_dst + r * (SROW * 2) + lc * 16,
                       xg + (size_t)r * Hn + lc * 8);
        }
#pragma unroll
        for (int j = 0; j < 2; j++) {
            int r = lr + j * 64;
            cp_async16(b_dst + r * (SROW * 2) + lc * 16,
                       wg + (size_t)r * Hn + lc * 8);
        }
        CP_COMMIT();
    };

    float acc[2][8][4];
#pragma unroll
    for (int mf = 0; mf < 2; mf++)
#pragma unroll
        for (int nf = 0; nf < 8; nf++)
#pragma unroll
            for (int k = 0; k < 4; k++) acc[mf][nf][k] = 0.f;

    // precomputed ldmatrix lane addresses (offsets within a buffer)
    // A: row = warpM*32 + mf*16 + (lane&15), k-col = (lane>>4)*8
    const uint32_t a_lane_off =
        (uint32_t)((warpM * 32 + (lane & 15)) * (SROW * 2) + (lane >> 4) * 16);
    // B: grp = lane>>3: n += (grp&2?8:0)+rw, k += (grp&1?8:0)
    const int b_grp = lane >> 3, b_rw = lane & 7;
    const uint32_t b_lane_off =
        (uint32_t)((warpN * 64 + ((b_grp & 2) ? 8 : 0) + b_rw) * (SROW * 2) +
                   ((b_grp & 1) ? 16 : 0));

    issue_load(0, 0);

#pragma unroll 1
    for (int i = 0; i < KITERS; i++) {
        const int cur = i & 1;
        if (i + 1 < KITERS) {
            issue_load(cur ^ 1, i + 1);
            CP_WAIT(1);
        } else {
            CP_WAIT(0);
        }
        __syncthreads();

        const uint32_t aB = sA_base + cur * BUF_A;
        const uint32_t bB = sB_base + cur * BUF_B;
#pragma unroll
        for (int ks = 0; ks < 2; ks++) {
            uint32_t a[2][4];
#pragma unroll
            for (int mf = 0; mf < 2; mf++) {
                ldsm_x4(a[mf][0], a[mf][1], a[mf][2], a[mf][3],
                        aB + a_lane_off + mf * 16 * (SROW * 2) + ks * 32);
            }
            uint32_t b[4][4];
#pragma unroll
            for (int nf2 = 0; nf2 < 4; nf2++) {
                ldsm_x4(b[nf2][0], b[nf2][1], b[nf2][2], b[nf2][3],
                        bB + b_lane_off + nf2 * 16 * (SROW * 2) + ks * 32);
            }
#pragma unroll
            for (int mf = 0; mf < 2; mf++) {
#pragma unroll
                for (int nf2 = 0; nf2 < 4; nf2++) {
                    mma16816(acc[mf][nf2 * 2][0], acc[mf][nf2 * 2][1],
                             acc[mf][nf2 * 2][2], acc[mf][nf2 * 2][3],
                             a[mf][0], a[mf][1], a[mf][2], a[mf][3],
                             b[nf2][0], b[nf2][1]);
                    mma16816(acc[mf][nf2 * 2 + 1][0], acc[mf][nf2 * 2 + 1][1],
                             acc[mf][nf2 * 2 + 1][2], acc[mf][nf2 * 2 + 1][3],
                             a[mf][0], a[mf][1], a[mf][2], a[mf][3],
                             b[nf2][2], b[nf2][3]);
                }
            }
        }
        __syncthreads();
    }

    // ---- epilogue: exp + row sums + selected-logit capture ----
    const int gq = lane >> 2;  // 0..7 row group
#pragma unroll
    for (int mf = 0; mf < 2; mf++) {
        const int row0 = warpM * 32 + mf * 16 + gq;
        const int row1 = row0 + 8;
        const int sid0 = sel_ids[m0 + row0];
        const int sid1 = sel_ids[m0 + row1];
        float se0 = 0.f, se1 = 0.f;
#pragma unroll
        for (int nf = 0; nf < 8; nf++) {
            const float v0 = acc[mf][nf][0], v1 = acc[mf][nf][1];
            const float v2 = acc[mf][nf][2], v3 = acc[mf][nf][3];
            const int colb = n0 + warpN * 64 + nf * 8 + (lane & 3) * 2;
            se0 += __expf(v0) + __expf(v1);
            se1 += __expf(v2) + __expf(v3);
            if (colb == sid0)     g_sel[gz][m0 + row0] = v0;
            if (colb + 1 == sid0) g_sel[gz][m0 + row0] = v1;
            if (colb == sid1)     g_sel[gz][m0 + row1] = v2;
            if (colb + 1 == sid1) g_sel[gz][m0 + row1] = v3;
        }
        se0 += __shfl_xor_sync(0xFFFFFFFF, se0, 1);
        se0 += __shfl_xor_sync(0xFFFFFFFF, se0, 2);
        se1 += __shfl_xor_sync(0xFFFFFFFF, se1, 1);
        se1 += __shfl_xor_sync(0xFFFFFFFF, se1, 2);
        if ((lane & 3) == 0) {
            rsum[warpN][row0] = se0;
            rsum[warpN][row1] = se1;
        }
    }
    __syncthreads();
    if (tid < M_TILE) {
        g_partial[gz][nt][m0 + tid] = rsum[0][tid] + rsum[1][tid];
    }
}

// ---------------- per-token LSE / logp ----------------
__global__ void lse_kernel() {
    const int idx = blockIdx.x * blockDim.x + threadIdx.x;
    if (idx >= 2 * TOK) return;
    const int g = idx / TOK;
    const int t = idx % TOK;
    float s = 0.f;
#pragma unroll 5
    for (int nt = 0; nt < NTILES; nt++) s += g_partial[g][nt][t];
    g_logp[g][t] = g_sel[g][t] - logf(s);
}

// ---------------- final scalar loss ----------------
__global__ void loss_kernel(const int* __restrict__ mask,
                            const float* __restrict__ adv,
                            const float* __restrict__ oldlp,
                            float* __restrict__ out) {
    __shared__ double sh[256], shm[256];
    double acc = 0.0, macc = 0.0;
    for (int t = threadIdx.x; t < TOK; t += 256) {
        const float per = g_logp[0][t];
        const float ref = g_logp[1][t];
        const float old = oldlp[t];
        const float a = adv[t / Tn];
        const float c1 = expf(per - old);
        const float c2 = fminf(fmaxf(c1, 1.0f - 0.2f), 1.0f + 0.2f);
        const float pl = -fminf(c1 * a, c2 * a);
        const float d = ref - per;
        const float kl = expf(d) - d - 1.0f;
        const float m = (float)mask[t];
        acc += (double)((pl + 0.1f * kl) * m);
        macc += (double)m;
    }
    sh[threadIdx.x] = acc;
    shm[threadIdx.x] = macc;
    __syncthreads();
    for (int s = 128; s > 0; s >>= 1) {
        if (threadIdx.x < s) {
            sh[threadIdx.x] += sh[threadIdx.x + s];
            shm[threadIdx.x] += shm[threadIdx.x + s];
        }
        __syncthreads();
    }
    if (threadIdx.x == 0) out[0] = (float)(sh[0] / fmax(shm[0], 1.0));
}

// ---------------- launch ----------------
extern "C" void kernel_launch(void* const* d_in, const int* in_sizes, int n_in,
                              void* d_out, int out_size) {
    const float* x     = (const float*)d_in[0];
    const float* rx    = (const float*)d_in[1];
    const float* w     = (const float*)d_in[2];
    const float* rw    = (const float*)d_in[3];
    const int*   sel   = (const int*)d_in[4];
    const int*   mask  = (const int*)d_in[5];
    const float* adv   = (const float*)d_in[6];
    const float* oldlp = (const float*)d_in[7];
    float* out = (float*)d_out;

    __half* wh0;  cudaGetSymbolAddress((void**)&wh0, g_wh);
    __half* xh0;  cudaGetSymbolAddress((void**)&xh0, g_xh);

    convert_kernel<<<512, 256>>>(x,  xh0,                         TOK * Hn / 4);
    convert_kernel<<<512, 256>>>(rx, xh0 + (size_t)TOK * Hn,      TOK * Hn / 4);
    convert_kernel<<<2048, 256>>>(w,  wh0,                        Vn * Hn / 4);
    convert_kernel<<<2048, 256>>>(rw, wh0 + (size_t)Vn * Hn,      Vn * Hn / 4);

    gemm_kernel<<<dim3(MTILES, NTILES, 2), 256>>>(sel);

    lse_kernel<<<(2 * TOK + 255) / 256, 256>>>();
    loss_kernel<<<1, 256>>>(mask, adv, oldlp, out);
}

// round 3
// speedup vs baseline: 1.3996x; 1.3996x over previous
#include <cuda_runtime.h>
#include <cuda_fp16.h>
#include <cstdint>

// ---------------- problem constants ----------------
constexpr int Bn = 4, Tn = 1024, Hn = 2048, Vn = 32000;
constexpr int TOK = Bn * Tn;            // 4096 tokens
constexpr int M_TILE = 128;
constexpr int N_TILE = 256;
constexpr int K_CHUNK = 64;
constexpr int MTILES = TOK / M_TILE;    // 32
constexpr int NTILES = Vn / N_TILE;     // 125
constexpr int KITERS = Hn / K_CHUNK;    // 32

// smem row: 64 halves + 8 pad = 72 halves (144 B) -> conflict-free ldmatrix
constexpr int SROW = 72;
constexpr uint32_t BUF_A = M_TILE * SROW * 2;          // 18432 B
constexpr uint32_t BUF_B = N_TILE * SROW * 2;          // 36864 B
constexpr uint32_t STAGE = BUF_A + BUF_B;              // 55296 B
constexpr uint32_t SMEM_BYTES = 2 * STAGE;             // 110592 B

// ---------------- device scratch (no runtime alloc allowed) ----------------
__device__ __half g_wh[2][(size_t)Vn * Hn];   // fp16 weights (policy, ref)
__device__ __half g_xh[2][(size_t)TOK * Hn];  // fp16 activations
__device__ float  g_partial[2][NTILES][TOK];  // per-ntile partial sumexp
__device__ float  g_sel[2][TOK];              // selected logits
__device__ float  g_logp[2][TOK];             // per-token logps

// ---------------- PTX helpers (baseline features only) ----------------
__device__ __forceinline__ uint32_t smem_u32(const void* p) {
    uint32_t a;
    asm("{ .reg .u64 t; cvta.to.shared.u64 t, %1; cvt.u32.u64 %0, t; }" : "=r"(a) : "l"(p));
    return a;
}

__device__ __forceinline__ void cp_async16(uint32_t dst, const void* src) {
    asm volatile("cp.async.cg.shared.global [%0], [%1], 16;" :: "r"(dst), "l"(src) : "memory");
}
#define CP_COMMIT() asm volatile("cp.async.commit_group;" ::: "memory")
#define CP_WAIT_ALL() asm volatile("cp.async.wait_group 0;" ::: "memory")

__device__ __forceinline__ void ldsm_x4(uint32_t& r0, uint32_t& r1, uint32_t& r2, uint32_t& r3,
                                        uint32_t addr) {
    asm volatile("ldmatrix.sync.aligned.m8n8.x4.shared.b16 {%0,%1,%2,%3}, [%4];"
                 : "=r"(r0), "=r"(r1), "=r"(r2), "=r"(r3) : "r"(addr));
}

__device__ __forceinline__ void mma16816(float& d0, float& d1, float& d2, float& d3,
                                         uint32_t a0, uint32_t a1, uint32_t a2, uint32_t a3,
                                         uint32_t b0, uint32_t b1) {
    asm volatile(
        "mma.sync.aligned.m16n8k16.row.col.f32.f16.f16.f32 "
        "{%0,%1,%2,%3}, {%4,%5,%6,%7}, {%8,%9}, {%0,%1,%2,%3};"
        : "+f"(d0), "+f"(d1), "+f"(d2), "+f"(d3)
        : "r"(a0), "r"(a1), "r"(a2), "r"(a3), "r"(b0), "r"(b1));
}

// ---------------- convert kernels (fp32 -> fp16 scratch) ----------------
__global__ void convert_kernel(const float* __restrict__ src, __half* __restrict__ dst,
                               int n4) {
    int i = blockIdx.x * blockDim.x + threadIdx.x;
    const int stride = gridDim.x * blockDim.x;
    for (; i < n4; i += stride) {
        float4 v = reinterpret_cast<const float4*>(src)[i];
        __half2 lo = __floats2half2_rn(v.x, v.y);
        __half2 hi = __floats2half2_rn(v.z, v.w);
        uint2 o;
        o.x = reinterpret_cast<uint32_t&>(lo);
        o.y = reinterpret_cast<uint32_t&>(hi);
        reinterpret_cast<uint2*>(dst)[i] = o;
    }
}

// ---------------- fused GEMM + partial-softmax kernel ----------------
// grid = (MTILES, NTILES, 2); block = 256 threads (8 warps: 2 M x 4 N, warp tile 64x64)
__global__ void __launch_bounds__(256, 1) gemm_kernel(const int* __restrict__ sel_ids) {
    extern __shared__ __align__(16) char dsm[];
    const uint32_t sbase = smem_u32(dsm);

    const int tid = threadIdx.x;
    const int lane = tid & 31;
    const int wid = tid >> 5;
    const int warpM = wid >> 2;   // 0..1  (64 rows each)
    const int warpN = wid & 3;    // 0..3  (64 cols each)
    const int gz = blockIdx.z;
    const int nt = blockIdx.y;
    const int m0 = blockIdx.x * M_TILE;
    const int n0 = nt * N_TILE;

    const __half* __restrict__ X = g_xh[gz];
    const __half* __restrict__ W = g_wh[gz];

    // cp.async loader: A = 1024 chunks of 16B, B = 2048 chunks; 256 threads
    auto issue_load = [&](int p, int ki) {
        const __half* xg = X + (size_t)m0 * Hn + ki * K_CHUNK;
        const __half* wg = W + (size_t)n0 * Hn + ki * K_CHUNK;
        const uint32_t a_dst = sbase + p * STAGE;
        const uint32_t b_dst = sbase + p * STAGE + BUF_A;
#pragma unroll
        for (int j = 0; j < 4; j++) {
            int id = tid + j * 256;
            int r = id >> 3, c = id & 7;
            cp_async16(a_dst + r * (SROW * 2) + c * 16, xg + (size_t)r * Hn + c * 8);
        }
#pragma unroll
        for (int j = 0; j < 8; j++) {
            int id = tid + j * 256;
            int r = id >> 3, c = id & 7;
            cp_async16(b_dst + r * (SROW * 2) + c * 16, wg + (size_t)r * Hn + c * 8);
        }
        CP_COMMIT();
    };

    float acc[4][8][4];
#pragma unroll
    for (int mf = 0; mf < 4; mf++)
#pragma unroll
        for (int nf = 0; nf < 8; nf++)
#pragma unroll
            for (int k = 0; k < 4; k++) acc[mf][nf][k] = 0.f;

    // ldmatrix lane offsets within a stage
    const uint32_t a_lane_off =
        (uint32_t)((warpM * 64 + (lane & 15)) * (SROW * 2) + (lane >> 4) * 16);
    const int b_grp = lane >> 3, b_rw = lane & 7;
    const uint32_t b_lane_off = BUF_A +
        (uint32_t)((warpN * 64 + ((b_grp & 2) ? 8 : 0) + b_rw) * (SROW * 2) +
                   ((b_grp & 1) ? 16 : 0));

    issue_load(0, 0);

#pragma unroll 1
    for (int i = 0; i < KITERS; i++) {
        const int cur = i & 1;
        CP_WAIT_ALL();            // all issued loads (incl. stage cur) landed
        __syncthreads();          // visible to all; all warps done with buffer cur^1
        if (i + 1 < KITERS) issue_load(cur ^ 1, i + 1);

        const uint32_t stage_base = sbase + cur * STAGE;
#pragma unroll
        for (int ks = 0; ks < 4; ks++) {
            uint32_t a[4][4];
#pragma unroll
            for (int mf = 0; mf < 4; mf++) {
                ldsm_x4(a[mf][0], a[mf][1], a[mf][2], a[mf][3],
                        stage_base + a_lane_off + mf * 16 * (SROW * 2) + ks * 32);
            }
            uint32_t b[4][4];
#pragma unroll
            for (int nf2 = 0; nf2 < 4; nf2++) {
                ldsm_x4(b[nf2][0], b[nf2][1], b[nf2][2], b[nf2][3],
                        stage_base + b_lane_off + nf2 * 16 * (SROW * 2) + ks * 32);
            }
#pragma unroll
            for (int mf = 0; mf < 4; mf++) {
#pragma unroll
                for (int nf2 = 0; nf2 < 4; nf2++) {
                    mma16816(acc[mf][nf2 * 2][0], acc[mf][nf2 * 2][1],
                             acc[mf][nf2 * 2][2], acc[mf][nf2 * 2][3],
                             a[mf][0], a[mf][1], a[mf][2], a[mf][3],
                             b[nf2][0], b[nf2][1]);
                    mma16816(acc[mf][nf2 * 2 + 1][0], acc[mf][nf2 * 2 + 1][1],
                             acc[mf][nf2 * 2 + 1][2], acc[mf][nf2 * 2 + 1][3],
                             a[mf][0], a[mf][1], a[mf][2], a[mf][3],
                             b[nf2][2], b[nf2][3]);
                }
            }
        }
        __syncthreads();          // warps done reading cur before next overwrite wave
    }

    // ---- epilogue: exp + row sums + selected-logit capture ----
    float* rsum = reinterpret_cast<float*>(dsm);   // [4 warpN][128 rows]
    const int gq = lane >> 2;  // 0..7
#pragma unroll
    for (int mf = 0; mf < 4; mf++) {
        const int row0 = warpM * 64 + mf * 16 + gq;
        const int row1 = row0 + 8;
        const int sid0 = sel_ids[m0 + row0];
        const int sid1 = sel_ids[m0 + row1];
        float se0 = 0.f, se1 = 0.f;
#pragma unroll
        for (int nf = 0; nf < 8; nf++) {
            const float v0 = acc[mf][nf][0], v1 = acc[mf][nf][1];
            const float v2 = acc[mf][nf][2], v3 = acc[mf][nf][3];
            const int colb = n0 + warpN * 64 + nf * 8 + (lane & 3) * 2;
            se0 += __expf(v0) + __expf(v1);
            se1 += __expf(v2) + __expf(v3);
            if (colb == sid0)     g_sel[gz][m0 + row0] = v0;
            if (colb + 1 == sid0) g_sel[gz][m0 + row0] = v1;
            if (colb == sid1)     g_sel[gz][m0 + row1] = v2;
            if (colb + 1 == sid1) g_sel[gz][m0 + row1] = v3;
        }
        se0 += __shfl_xor_sync(0xFFFFFFFF, se0, 1);
        se0 += __shfl_xor_sync(0xFFFFFFFF, se0, 2);
        se1 += __shfl_xor_sync(0xFFFFFFFF, se1, 1);
        se1 += __shfl_xor_sync(0xFFFFFFFF, se1, 2);
        if ((lane & 3) == 0) {
            rsum[warpN * M_TILE + row0] = se0;
            rsum[warpN * M_TILE + row1] = se1;
        }
    }
    __syncthreads();
    if (tid < M_TILE) {
        g_partial[gz][nt][m0 + tid] = rsum[0 * M_TILE + tid] + rsum[1 * M_TILE + tid] +
                                      rsum[2 * M_TILE + tid] + rsum[3 * M_TILE + tid];
    }
}

// ---------------- per-token LSE / logp ----------------
__global__ void lse_kernel() {
    const int idx = blockIdx.x * blockDim.x + threadIdx.x;
    if (idx >= 2 * TOK) return;
    const int g = idx / TOK;
    const int t = idx % TOK;
    float s = 0.f;
#pragma unroll 5
    for (int nt = 0; nt < NTILES; nt++) s += g_partial[g][nt][t];
    g_logp[g][t] = g_sel[g][t] - logf(s);
}

// ---------------- final scalar loss ----------------
__global__ void loss_kernel(const int* __restrict__ mask,
                            const float* __restrict__ adv,
                            const float* __restrict__ oldlp,
                            float* __restrict__ out) {
    __shared__ double sh[256], shm[256];
    double acc = 0.0, macc = 0.0;
    for (int t = threadIdx.x; t < TOK; t += 256) {
        const float per = g_logp[0][t];
        const float ref = g_logp[1][t];
        const float old = oldlp[t];
        const float a = adv[t / Tn];
        const float c1 = expf(per - old);
        const float c2 = fminf(fmaxf(c1, 1.0f - 0.2f), 1.0f + 0.2f);
        const float pl = -fminf(c1 * a, c2 * a);
        const float d = ref - per;
        const float kl = expf(d) - d - 1.0f;
        const float m = (float)mask[t];
        acc += (double)((pl + 0.1f * kl) * m);
        macc += (double)m;
    }
    sh[threadIdx.x] = acc;
    shm[threadIdx.x] = macc;
    __syncthreads();
    for (int s = 128; s > 0; s >>= 1) {
        if (threadIdx.x < s) {
            sh[threadIdx.x] += sh[threadIdx.x + s];
            shm[threadIdx.x] += shm[threadIdx.x + s];
        }
        __syncthreads();
    }
    if (threadIdx.x == 0) out[0] = (float)(sh[0] / fmax(shm[0], 1.0));
}

// ---------------- launch ----------------
extern "C" void kernel_launch(void* const* d_in, const int* in_sizes, int n_in,
                              void* d_out, int out_size) {
    const float* x     = (const float*)d_in[0];
    const float* rx    = (const float*)d_in[1];
    const float* w     = (const float*)d_in[2];
    const float* rw    = (const float*)d_in[3];
    const int*   sel   = (const int*)d_in[4];
    const int*   mask  = (const int*)d_in[5];
    const float* adv   = (const float*)d_in[6];
    const float* oldlp = (const float*)d_in[7];
    float* out = (float*)d_out;

    __half* wh0;  cudaGetSymbolAddress((void**)&wh0, g_wh);
    __half* xh0;  cudaGetSymbolAddress((void**)&xh0, g_xh);

    cudaFuncSetAttribute(gemm_kernel, cudaFuncAttributeMaxDynamicSharedMemorySize, SMEM_BYTES);

    convert_kernel<<<512, 256>>>(x,  xh0,                    TOK * Hn / 4);
    convert_kernel<<<512, 256>>>(rx, xh0 + (size_t)TOK * Hn, TOK * Hn / 4);
    convert_kernel<<<2048, 256>>>(w,  wh0,                   Vn * Hn / 4);
    convert_kernel<<<2048, 256>>>(rw, wh0 + (size_t)Vn * Hn, Vn * Hn / 4);

    gemm_kernel<<<dim3(MTILES, NTILES, 2), 256, SMEM_BYTES>>>(sel);

    lse_kernel<<<(2 * TOK + 255) / 256, 256>>>();
    loss_kernel<<<1, 256>>>(mask, adv, oldlp, out);
}

// round 4
// speedup vs baseline: 1.4213x; 1.0155x over previous
#include <cuda_runtime.h>
#include <cuda_fp16.h>
#include <cstdint>

// ---------------- problem constants ----------------
constexpr int Bn = 4, Tn = 1024, Hn = 2048, Vn = 32000;
constexpr int TOK = Bn * Tn;            // 4096 tokens
constexpr int M_TILE = 128;
constexpr int N_TILE = 256;
constexpr int K_CHUNK = 64;
constexpr int MTILES = TOK / M_TILE;    // 32
constexpr int NTILES = Vn / N_TILE;     // 125
constexpr int KITERS = Hn / K_CHUNK;    // 32
constexpr int STAGES = 4;

// smem row: 64 halves + 8 pad = 72 halves (144 B) -> conflict-free ldmatrix
constexpr int SROW = 72;
constexpr uint32_t BUF_A = M_TILE * SROW * 2;          // 18432 B
constexpr uint32_t BUF_B = N_TILE * SROW * 2;          // 36864 B
constexpr uint32_t STAGE = BUF_A + BUF_B;              // 55296 B
constexpr uint32_t SMEM_BYTES = STAGES * STAGE;        // 221184 B

// ---------------- device scratch (no runtime alloc allowed) ----------------
__device__ __half g_wh[2][(size_t)Vn * Hn];   // fp16 weights (policy, ref)
__device__ __half g_xh[2][(size_t)TOK * Hn];  // fp16 activations
__device__ float  g_partial[2][NTILES][TOK];  // per-ntile partial sumexp
__device__ float  g_sel[2][TOK];              // selected logits
__device__ float  g_logp[2][TOK];             // per-token logps

// ---------------- PTX helpers (baseline features only) ----------------
__device__ __forceinline__ uint32_t smem_u32(const void* p) {
    uint32_t a;
    asm("{ .reg .u64 t; cvta.to.shared.u64 t, %1; cvt.u32.u64 %0, t; }" : "=r"(a) : "l"(p));
    return a;
}

__device__ __forceinline__ void cp_async16(uint32_t dst, const void* src) {
    asm volatile("cp.async.cg.shared.global [%0], [%1], 16;" :: "r"(dst), "l"(src) : "memory");
}
#define CP_COMMIT() asm volatile("cp.async.commit_group;" ::: "memory")

__device__ __forceinline__ void ldsm_x4(uint32_t& r0, uint32_t& r1, uint32_t& r2, uint32_t& r3,
                                        uint32_t addr) {
    asm volatile("ldmatrix.sync.aligned.m8n8.x4.shared.b16 {%0,%1,%2,%3}, [%4];"
                 : "=r"(r0), "=r"(r1), "=r"(r2), "=r"(r3) : "r"(addr));
}

__device__ __forceinline__ void mma16816(float& d0, float& d1, float& d2, float& d3,
                                         uint32_t a0, uint32_t a1, uint32_t a2, uint32_t a3,
                                         uint32_t b0, uint32_t b1) {
    asm volatile(
        "mma.sync.aligned.m16n8k16.row.col.f32.f16.f16.f32 "
        "{%0,%1,%2,%3}, {%4,%5,%6,%7}, {%8,%9}, {%0,%1,%2,%3};"
        : "+f"(d0), "+f"(d1), "+f"(d2), "+f"(d3)
        : "r"(a0), "r"(a1), "r"(a2), "r"(a3), "r"(b0), "r"(b1));
}

// ---------------- fused convert kernel (fp32 -> fp16, all 4 arrays) ----------------
__global__ void convert_all_kernel(const float* __restrict__ x, const float* __restrict__ rx,
                                   const float* __restrict__ w, const float* __restrict__ rw) {
    constexpr int NX = TOK * Hn / 4;   // float4 count per X array
    constexpr int NW = Vn * Hn / 4;
    constexpr int TOTAL = 2 * NX + 2 * NW;
    __half* xh = g_xh[0];
    __half* wh = g_wh[0];
    int i = blockIdx.x * blockDim.x + threadIdx.x;
    const int stride = gridDim.x * blockDim.x;
    for (; i < TOTAL; i += stride) {
        const float* src;
        __half* dst;
        int j = i;
        if (j < 2 * NW) {
            if (j < NW) { src = w; dst = wh; }
            else        { src = rw; dst = wh + (size_t)Vn * Hn; j -= NW; }
        } else {
            j -= 2 * NW;
            if (j < NX) { src = x; dst = xh; }
            else        { src = rx; dst = xh + (size_t)TOK * Hn; j -= NX; }
        }
        float4 v = reinterpret_cast<const float4*>(src)[j];
        __half2 lo = __floats2half2_rn(v.x, v.y);
        __half2 hi = __floats2half2_rn(v.z, v.w);
        uint2 o;
        o.x = reinterpret_cast<uint32_t&>(lo);
        o.y = reinterpret_cast<uint32_t&>(hi);
        reinterpret_cast<uint2*>(dst)[j] = o;
    }
}

// ---------------- fused GEMM + partial-softmax kernel ----------------
// grid = (MTILES, NTILES, 2); block = 256 threads (8 warps: 2 M x 4 N, warp tile 64x64)
__global__ void __launch_bounds__(256, 1) gemm_kernel(const int* __restrict__ sel_ids) {
    extern __shared__ __align__(16) char dsm[];
    const uint32_t sbase = smem_u32(dsm);

    const int tid = threadIdx.x;
    const int lane = tid & 31;
    const int wid = tid >> 5;
    const int warpM = wid >> 2;   // 0..1  (64 rows each)
    const int warpN = wid & 3;    // 0..3  (64 cols each)
    const int gz = blockIdx.z;
    const int nt = blockIdx.y;
    const int m0 = blockIdx.x * M_TILE;
    const int n0 = nt * N_TILE;

    const __half* __restrict__ X = g_xh[gz];
    const __half* __restrict__ W = g_wh[gz];

    auto issue_load = [&](int p, int ki) {
        const __half* xg = X + (size_t)m0 * Hn + ki * K_CHUNK;
        const __half* wg = W + (size_t)n0 * Hn + ki * K_CHUNK;
        const uint32_t a_dst = sbase + p * STAGE;
        const uint32_t b_dst = a_dst + BUF_A;
#pragma unroll
        for (int j = 0; j < 4; j++) {
            int id = tid + j * 256;
            int r = id >> 3, c = id & 7;
            cp_async16(a_dst + r * (SROW * 2) + c * 16, xg + (size_t)r * Hn + c * 8);
        }
#pragma unroll
        for (int j = 0; j < 8; j++) {
            int id = tid + j * 256;
            int r = id >> 3, c = id & 7;
            cp_async16(b_dst + r * (SROW * 2) + c * 16, wg + (size_t)r * Hn + c * 8);
        }
        CP_COMMIT();
    };

    float acc[4][8][4];
#pragma unroll
    for (int mf = 0; mf < 4; mf++)
#pragma unroll
        for (int nf = 0; nf < 8; nf++)
#pragma unroll
            for (int k = 0; k < 4; k++) acc[mf][nf][k] = 0.f;

    const uint32_t a_lane_off =
        (uint32_t)((warpM * 64 + (lane & 15)) * (SROW * 2) + (lane >> 4) * 16);
    const int b_grp = lane >> 3, b_rw = lane & 7;
    const uint32_t b_lane_off = BUF_A +
        (uint32_t)((warpN * 64 + ((b_grp & 2) ? 8 : 0) + b_rw) * (SROW * 2) +
                   ((b_grp & 1) ? 16 : 0));

    issue_load(0, 0);
    issue_load(1, 1);
    issue_load(2, 2);

#pragma unroll 1
    for (int i = 0; i < KITERS; i++) {
        // retire group i: allow (#remaining-issued-after-i) outstanding
        const int rem = KITERS - 1 - i;
        if (rem >= 2)      asm volatile("cp.async.wait_group 2;" ::: "memory");
        else if (rem == 1) asm volatile("cp.async.wait_group 1;" ::: "memory");
        else               asm volatile("cp.async.wait_group 0;" ::: "memory");
        __syncthreads();   // stage i visible to all; all warps done with stage (i-1)

        if (i + 3 < KITERS) issue_load((i + 3) & 3, i + 3);

        const uint32_t stage_base = sbase + (i & 3) * STAGE;
#pragma unroll
        for (int ks = 0; ks < 4; ks++) {
            uint32_t a[4][4];
#pragma unroll
            for (int mf = 0; mf < 4; mf++) {
                ldsm_x4(a[mf][0], a[mf][1], a[mf][2], a[mf][3],
                        stage_base + a_lane_off + mf * 16 * (SROW * 2) + ks * 32);
            }
            uint32_t b[4][4];
#pragma unroll
            for (int nf2 = 0; nf2 < 4; nf2++) {
                ldsm_x4(b[nf2][0], b[nf2][1], b[nf2][2], b[nf2][3],
                        stage_base + b_lane_off + nf2 * 16 * (SROW * 2) + ks * 32);
            }
#pragma unroll
            for (int mf = 0; mf < 4; mf++) {
#pragma unroll
                for (int nf2 = 0; nf2 < 4; nf2++) {
                    mma16816(acc[mf][nf2 * 2][0], acc[mf][nf2 * 2][1],
                             acc[mf][nf2 * 2][2], acc[mf][nf2 * 2][3],
                             a[mf][0], a[mf][1], a[mf][2], a[mf][3],
                             b[nf2][0], b[nf2][1]);
                    mma16816(acc[mf][nf2 * 2 + 1][0], acc[mf][nf2 * 2 + 1][1],
                             acc[mf][nf2 * 2 + 1][2], acc[mf][nf2 * 2 + 1][3],
                             a[mf][0], a[mf][1], a[mf][2], a[mf][3],
                             b[nf2][2], b[nf2][3]);
                }
            }
        }
    }

    // ---- epilogue: exp + row sums + selected-logit capture ----
    float* rsum = reinterpret_cast<float*>(dsm);   // [4 warpN][128 rows] (stage-0 region, quiesced)
    const int gq = lane >> 2;  // 0..7
#pragma unroll
    for (int mf = 0; mf < 4; mf++) {
        const int row0 = warpM * 64 + mf * 16 + gq;
        const int row1 = row0 + 8;
        const int sid0 = sel_ids[m0 + row0];
        const int sid1 = sel_ids[m0 + row1];
        float se0 = 0.f, se1 = 0.f;
#pragma unroll
        for (int nf = 0; nf < 8; nf++) {
            const float v0 = acc[mf][nf][0], v1 = acc[mf][nf][1];
            const float v2 = acc[mf][nf][2], v3 = acc[mf][nf][3];
            const int colb = n0 + warpN * 64 + nf * 8 + (lane & 3) * 2;
            se0 += __expf(v0) + __expf(v1);
            se1 += __expf(v2) + __expf(v3);
            if (colb == sid0)     g_sel[gz][m0 + row0] = v0;
            if (colb + 1 == sid0) g_sel[gz][m0 + row0] = v1;
            if (colb == sid1)     g_sel[gz][m0 + row1] = v2;
            if (colb + 1 == sid1) g_sel[gz][m0 + row1] = v3;
        }
        se0 += __shfl_xor_sync(0xFFFFFFFF, se0, 1);
        se0 += __shfl_xor_sync(0xFFFFFFFF, se0, 2);
        se1 += __shfl_xor_sync(0xFFFFFFFF, se1, 1);
        se1 += __shfl_xor_sync(0xFFFFFFFF, se1, 2);
        if ((lane & 3) == 0) {
            rsum[warpN * M_TILE + row0] = se0;
            rsum[warpN * M_TILE + row1] = se1;
        }
    }
    __syncthreads();
    if (tid < M_TILE) {
        g_partial[gz][nt][m0 + tid] = rsum[0 * M_TILE + tid] + rsum[1 * M_TILE + tid] +
                                      rsum[2 * M_TILE + tid] + rsum[3 * M_TILE + tid];
    }
}

// ---------------- per-token LSE / logp ----------------
__global__ void lse_kernel() {
    const int idx = blockIdx.x * blockDim.x + threadIdx.x;
    if (idx >= 2 * TOK) return;
    const int g = idx / TOK;
    const int t = idx % TOK;
    float s = 0.f;
#pragma unroll 5
    for (int nt = 0; nt < NTILES; nt++) s += g_partial[g][nt][t];
    g_logp[g][t] = g_sel[g][t] - logf(s);
}

// ---------------- final scalar loss ----------------
__global__ void loss_kernel(const int* __restrict__ mask,
                            const float* __restrict__ adv,
                            const float* __restrict__ oldlp,
                            float* __restrict__ out) {
    __shared__ double sh[256], shm[256];
    double acc = 0.0, macc = 0.0;
    for (int t = threadIdx.x; t < TOK; t += 256) {
        const float per = g_logp[0][t];
        const float ref = g_logp[1][t];
        const float old = oldlp[t];
        const float a = adv[t / Tn];
        const float c1 = expf(per - old);
        const float c2 = fminf(fmaxf(c1, 1.0f - 0.2f), 1.0f + 0.2f);
        const float pl = -fminf(c1 * a, c2 * a);
        const float d = ref - per;
        const float kl = expf(d) - d - 1.0f;
        const float m = (float)mask[t];
        acc += (double)((pl + 0.1f * kl) * m);
        macc += (double)m;
    }
    sh[threadIdx.x] = acc;
    shm[threadIdx.x] = macc;
    __syncthreads();
    for (int s = 128; s > 0; s >>= 1) {
        if (threadIdx.x < s) {
            sh[threadIdx.x] += sh[threadIdx.x + s];
            shm[threadIdx.x] += shm[threadIdx.x + s];
        }
        __syncthreads();
    }
    if (threadIdx.x == 0) out[0] = (float)(sh[0] / fmax(shm[0], 1.0));
}

// ---------------- launch ----------------
extern "C" void kernel_launch(void* const* d_in, const int* in_sizes, int n_in,
                              void* d_out, int out_size) {
    const float* x     = (const float*)d_in[0];
    const float* rx    = (const float*)d_in[1];
    const float* w     = (const float*)d_in[2];
    const float* rw    = (const float*)d_in[3];
    const int*   sel   = (const int*)d_in[4];
    const int*   mask  = (const int*)d_in[5];
    const float* adv   = (const float*)d_in[6];
    const float* oldlp = (const float*)d_in[7];
    float* out = (float*)d_out;

    cudaFuncSetAttribute(gemm_kernel, cudaFuncAttributeMaxDynamicSharedMemorySize, SMEM_BYTES);

    convert_all_kernel<<<4096, 256>>>(x, rx, w, rw);

    gemm_kernel<<<dim3(MTILES, NTILES, 2), 256, SMEM_BYTES>>>(sel);

    lse_kernel<<<(2 * TOK + 255) / 256, 256>>>();
    loss_kernel<<<1, 256>>>(mask, adv, oldlp, out);
}

// round 5
// speedup vs baseline: 1.5833x; 1.1140x over previous
#include <cuda_runtime.h>
#include <cuda_fp16.h>
#include <cstdint>

// ---------------- problem constants ----------------
constexpr int Bn = 4, Tn = 1024, Hn = 2048, Vn = 32000;
constexpr int TOK = Bn * Tn;            // 4096 tokens
constexpr int M_TILE = 128;
constexpr int N_TILE = 128;
constexpr int K_CHUNK = 64;
constexpr int MTILES = TOK / M_TILE;    // 32
constexpr int NTILES = Vn / N_TILE;     // 250
constexpr int KITERS = Hn / K_CHUNK;    // 32
constexpr int STAGES = 3;

// smem row: 64 halves + 8 pad = 72 halves (144 B) -> conflict-free ldmatrix
constexpr int SROW = 72;
constexpr uint32_t BUF_A = M_TILE * SROW * 2;          // 18432 B
constexpr uint32_t BUF_B = N_TILE * SROW * 2;          // 18432 B
constexpr uint32_t STAGE = BUF_A + BUF_B;              // 36864 B
constexpr uint32_t SMEM_BYTES = STAGES * STAGE;        // 110592 B per CTA

// ---------------- device scratch (no runtime alloc allowed) ----------------
__device__ __half g_wh[2][(size_t)Vn * Hn];   // fp16 weights (policy, ref)
__device__ __half g_xh[2][(size_t)TOK * Hn];  // fp16 activations
__device__ float  g_partial[2][NTILES][TOK];  // per-ntile partial sumexp
__device__ float  g_sel[2][TOK];              // selected logits
__device__ float  g_logp[2][TOK];             // per-token logps

// ---------------- PTX helpers (baseline features only) ----------------
__device__ __forceinline__ uint32_t smem_u32(const void* p) {
    uint32_t a;
    asm("{ .reg .u64 t; cvta.to.shared.u64 t, %1; cvt.u32.u64 %0, t; }" : "=r"(a) : "l"(p));
    return a;
}

__device__ __forceinline__ void cp_async16(uint32_t dst, const void* src) {
    asm volatile("cp.async.cg.shared.global [%0], [%1], 16;" :: "r"(dst), "l"(src) : "memory");
}
#define CP_COMMIT() asm volatile("cp.async.commit_group;" ::: "memory")

__device__ __forceinline__ void ldsm_x4(uint32_t& r0, uint32_t& r1, uint32_t& r2, uint32_t& r3,
                                        uint32_t addr) {
    asm volatile("ldmatrix.sync.aligned.m8n8.x4.shared.b16 {%0,%1,%2,%3}, [%4];"
                 : "=r"(r0), "=r"(r1), "=r"(r2), "=r"(r3) : "r"(addr));
}

__device__ __forceinline__ void mma16816(float& d0, float& d1, float& d2, float& d3,
                                         uint32_t a0, uint32_t a1, uint32_t a2, uint32_t a3,
                                         uint32_t b0, uint32_t b1) {
    asm volatile(
        "mma.sync.aligned.m16n8k16.row.col.f32.f16.f16.f32 "
        "{%0,%1,%2,%3}, {%4,%5,%6,%7}, {%8,%9}, {%0,%1,%2,%3};"
        : "+f"(d0), "+f"(d1), "+f"(d2), "+f"(d3)
        : "r"(a0), "r"(a1), "r"(a2), "r"(a3), "r"(b0), "r"(b1));
}

// ---------------- fused convert kernel (fp32 -> fp16, all 4 arrays) ----------------
__global__ void convert_all_kernel(const float* __restrict__ x, const float* __restrict__ rx,
                                   const float* __restrict__ w, const float* __restrict__ rw) {
    constexpr int NX = TOK * Hn / 4;
    constexpr int NW = Vn * Hn / 4;
    constexpr int TOTAL = 2 * NX + 2 * NW;
    __half* xh = g_xh[0];
    __half* wh = g_wh[0];
    int i = blockIdx.x * blockDim.x + threadIdx.x;
    const int stride = gridDim.x * blockDim.x;
    for (; i < TOTAL; i += stride) {
        const float* src;
        __half* dst;
        int j = i;
        if (j < 2 * NW) {
            if (j < NW) { src = w; dst = wh; }
            else        { src = rw; dst = wh + (size_t)Vn * Hn; j -= NW; }
        } else {
            j -= 2 * NW;
            if (j < NX) { src = x; dst = xh; }
            else        { src = rx; dst = xh + (size_t)TOK * Hn; j -= NX; }
        }
        float4 v = reinterpret_cast<const float4*>(src)[j];
        __half2 lo = __floats2half2_rn(v.x, v.y);
        __half2 hi = __floats2half2_rn(v.z, v.w);
        uint2 o;
        o.x = reinterpret_cast<uint32_t&>(lo);
        o.y = reinterpret_cast<uint32_t&>(hi);
        reinterpret_cast<uint2*>(dst)[j] = o;
    }
}

// ---------------- alignment no-op (puts gemm at the ncu-profiled slot) ----------------
__global__ void noop_kernel() {}

// ---------------- fused GEMM + partial-softmax kernel ----------------
// grid = (MTILES, NTILES, 2); block = 256 (8 warps: 2 M x 4 N, warp tile 64x32); 2 CTAs/SM
__global__ void __launch_bounds__(256, 2) gemm_kernel(const int* __restrict__ sel_ids) {
    extern __shared__ __align__(16) char dsm[];
    const uint32_t sbase = smem_u32(dsm);

    const int tid = threadIdx.x;
    const int lane = tid & 31;
    const int wid = tid >> 5;
    const int warpM = wid >> 2;   // 0..1  (64 rows each)
    const int warpN = wid & 3;    // 0..3  (32 cols each)
    const int gz = blockIdx.z;
    const int nt = blockIdx.y;
    const int m0 = blockIdx.x * M_TILE;
    const int n0 = nt * N_TILE;

    const __half* __restrict__ X = g_xh[gz];
    const __half* __restrict__ W = g_wh[gz];

    // loader: A and B each 128 rows x 64 halves = 1024 x 16B chunks; 4 per thread each
    auto issue_load = [&](int p, int ki) {
        const __half* xg = X + (size_t)m0 * Hn + ki * K_CHUNK;
        const __half* wg = W + (size_t)n0 * Hn + ki * K_CHUNK;
        const uint32_t a_dst = sbase + p * STAGE;
        const uint32_t b_dst = a_dst + BUF_A;
#pragma unroll
        for (int j = 0; j < 4; j++) {
            int id = tid + j * 256;
            int r = id >> 3, c = id & 7;
            cp_async16(a_dst + r * (SROW * 2) + c * 16, xg + (size_t)r * Hn + c * 8);
        }
#pragma unroll
        for (int j = 0; j < 4; j++) {
            int id = tid + j * 256;
            int r = id >> 3, c = id & 7;
            cp_async16(b_dst + r * (SROW * 2) + c * 16, wg + (size_t)r * Hn + c * 8);
        }
        CP_COMMIT();
    };

    float acc[4][4][4];
#pragma unroll
    for (int mf = 0; mf < 4; mf++)
#pragma unroll
        for (int nf = 0; nf < 4; nf++)
#pragma unroll
            for (int k = 0; k < 4; k++) acc[mf][nf][k] = 0.f;

    const uint32_t a_lane_off =
        (uint32_t)((warpM * 64 + (lane & 15)) * (SROW * 2) + (lane >> 4) * 16);
    const int b_grp = lane >> 3, b_rw = lane & 7;
    const uint32_t b_lane_off = BUF_A +
        (uint32_t)((warpN * 32 + ((b_grp & 2) ? 8 : 0) + b_rw) * (SROW * 2) +
                   ((b_grp & 1) ? 16 : 0));

    issue_load(0, 0);
    issue_load(1, 1);

#pragma unroll 1
    for (int i = 0; i < KITERS; i++) {
        if (i + 1 < KITERS) asm volatile("cp.async.wait_group 1;" ::: "memory");
        else                asm volatile("cp.async.wait_group 0;" ::: "memory");
        __syncthreads();   // stage i visible; all warps finished compute(i-1)

        if (i + 2 < KITERS) issue_load((i + 2) % STAGES, i + 2);

        const uint32_t stage_base = sbase + (i % STAGES) * STAGE;
#pragma unroll
        for (int ks = 0; ks < 4; ks++) {
            uint32_t a[4][4];
#pragma unroll
            for (int mf = 0; mf < 4; mf++) {
                ldsm_x4(a[mf][0], a[mf][1], a[mf][2], a[mf][3],
                        stage_base + a_lane_off + mf * 16 * (SROW * 2) + ks * 32);
            }
            uint32_t b[2][4];
#pragma unroll
            for (int nf2 = 0; nf2 < 2; nf2++) {
                ldsm_x4(b[nf2][0], b[nf2][1], b[nf2][2], b[nf2][3],
                        stage_base + b_lane_off + nf2 * 16 * (SROW * 2) + ks * 32);
            }
#pragma unroll
            for (int mf = 0; mf < 4; mf++) {
#pragma unroll
                for (int nf2 = 0; nf2 < 2; nf2++) {
                    mma16816(acc[mf][nf2 * 2][0], acc[mf][nf2 * 2][1],
                             acc[mf][nf2 * 2][2], acc[mf][nf2 * 2][3],
                             a[mf][0], a[mf][1], a[mf][2], a[mf][3],
                             b[nf2][0], b[nf2][1]);
                    mma16816(acc[mf][nf2 * 2 + 1][0], acc[mf][nf2 * 2 + 1][1],
                             acc[mf][nf2 * 2 + 1][2], acc[mf][nf2 * 2 + 1][3],
                             a[mf][0], a[mf][1], a[mf][2], a[mf][3],
                             b[nf2][2], b[nf2][3]);
                }
            }
        }
    }

    // ---- epilogue: exp + row sums + selected-logit capture ----
    __syncthreads();   // all compute done before reusing smem
    float* rsum = reinterpret_cast<float*>(dsm);   // [4 warpN][128 rows]
    const int gq = lane >> 2;  // 0..7
#pragma unroll
    for (int mf = 0; mf < 4; mf++) {
        const int row0 = warpM * 64 + mf * 16 + gq;
        const int row1 = row0 + 8;
        const int sid0 = sel_ids[m0 + row0];
        const int sid1 = sel_ids[m0 + row1];
        float se0 = 0.f, se1 = 0.f;
#pragma unroll
        for (int nf = 0; nf < 4; nf++) {
            const float v0 = acc[mf][nf][0], v1 = acc[mf][nf][1];
            const float v2 = acc[mf][nf][2], v3 = acc[mf][nf][3];
            const int colb = n0 + warpN * 32 + nf * 8 + (lane & 3) * 2;
            se0 += __expf(v0) + __expf(v1);
            se1 += __expf(v2) + __expf(v3);
            if (colb == sid0)     g_sel[gz][m0 + row0] = v0;
            if (colb + 1 == sid0) g_sel[gz][m0 + row0] = v1;
            if (colb == sid1)     g_sel[gz][m0 + row1] = v2;
            if (colb + 1 == sid1) g_sel[gz][m0 + row1] = v3;
        }
        se0 += __shfl_xor_sync(0xFFFFFFFF, se0, 1);
        se0 += __shfl_xor_sync(0xFFFFFFFF, se0, 2);
        se1 += __shfl_xor_sync(0xFFFFFFFF, se1, 1);
        se1 += __shfl_xor_sync(0xFFFFFFFF, se1, 2);
        if ((lane & 3) == 0) {
            rsum[warpN * M_TILE + row0] = se0;
            rsum[warpN * M_TILE + row1] = se1;
        }
    }
    __syncthreads();
    if (tid < M_TILE) {
        g_partial[gz][nt][m0 + tid] = rsum[0 * M_TILE + tid] + rsum[1 * M_TILE + tid] +
                                      rsum[2 * M_TILE + tid] + rsum[3 * M_TILE + tid];
    }
}

// ---------------- per-token LSE / logp ----------------
__global__ void lse_kernel() {
    const int idx = blockIdx.x * blockDim.x + threadIdx.x;
    if (idx >= 2 * TOK) return;
    const int g = idx / TOK;
    const int t = idx % TOK;
    float s = 0.f;
#pragma unroll 5
    for (int nt = 0; nt < NTILES; nt++) s += g_partial[g][nt][t];
    g_logp[g][t] = g_sel[g][t] - logf(s);
}

// ---------------- final scalar loss ----------------
__global__ void loss_kernel(const int* __restrict__ mask,
                            const float* __restrict__ adv,
                            const float* __restrict__ oldlp,
                            float* __restrict__ out) {
    __shared__ double sh[1024], shm[1024];
    double acc = 0.0, macc = 0.0;
    for (int t = threadIdx.x; t < TOK; t += 1024) {
        const float per = g_logp[0][t];
        const float ref = g_logp[1][t];
        const float old = oldlp[t];
        const float a = adv[t / Tn];
        const float c1 = expf(per - old);
        const float c2 = fminf(fmaxf(c1, 1.0f - 0.2f), 1.0f + 0.2f);
        const float pl = -fminf(c1 * a, c2 * a);
        const float d = ref - per;
        const float kl = expf(d) - d - 1.0f;
        const float m = (float)mask[t];
        acc += (double)((pl + 0.1f * kl) * m);
        macc += (double)m;
    }
    sh[threadIdx.x] = acc;
    shm[threadIdx.x] = macc;
    __syncthreads();
    for (int s = 512; s > 0; s >>= 1) {
        if (threadIdx.x < s) {
            sh[threadIdx.x] += sh[threadIdx.x + s];
            shm[threadIdx.x] += shm[threadIdx.x + s];
        }
        __syncthreads();
    }
    if (threadIdx.x == 0) out[0] = (float)(sh[0] / fmax(shm[0], 1.0));
}

// ---------------- launch ----------------
extern "C" void kernel_launch(void* const* d_in, const int* in_sizes, int n_in,
                              void* d_out, int out_size) {
    const float* x     = (const float*)d_in[0];
    const float* rx    = (const float*)d_in[1];
    const float* w     = (const float*)d_in[2];
    const float* rw    = (const float*)d_in[3];
    const int*   sel   = (const int*)d_in[4];
    const int*   mask  = (const int*)d_in[5];
    const float* adv   = (const float*)d_in[6];
    const float* oldlp = (const float*)d_in[7];
    float* out = (float*)d_out;

    cudaFuncSetAttribute(gemm_kernel, cudaFuncAttributeMaxDynamicSharedMemorySize, SMEM_BYTES);

    convert_all_kernel<<<4096, 256>>>(x, rx, w, rw);
    noop_kernel<<<1, 32>>>();
    noop_kernel<<<1, 32>>>();

    gemm_kernel<<<dim3(MTILES, NTILES, 2), 256, SMEM_BYTES>>>(sel);

    lse_kernel<<<(2 * TOK + 255) / 256, 256>>>();
    loss_kernel<<<1, 1024>>>(mask, adv, oldlp, out);
}